// round 10
// baseline (speedup 1.0000x reference)
#include <cuda_runtime.h>
#include <cstdint>

// Problem constants
#define NN 50000
#define RR 16
#define DD 200
#define EE 400000
#define NB (RR * NN)
#define S_MAX (EE + 256)
#define NBLK ((NB + 2047) / 2048)

#define TM 128
#define ROOT_TILES ((NN + TM - 1) / TM)    // 391
#define MAX_RTILES 3400

#define NP 216                  // padded N (3 warps x 72)
#define KK 200                  // K (g_Wt row length)
#define ASTRIDE 200             // A smem row stride (words): pair-LDS.64 2-phase clean
#define BSTRIDE 40              // B smem row stride (words): pair-LDS.64 2-phase clean

#define NTHREADS 384            // 12 warps: 4(M) x 3(N)

// smem byte offsets
#define SM_A   0
#define SM_ASZ (TM * ASTRIDE * 4)            // 102400
#define SM_B0  SM_ASZ
#define SM_BSZ (NP * BSTRIDE * 4)            // 34560
#define SM_B1  (SM_B0 + SM_BSZ)
#define SM_TOTAL (SM_B1 + SM_BSZ + 64)       // 171584

// ---------------- device scratch ----------------
__device__ int   g_cnt[NB];
__device__ int   g_slotid[NB];
__device__ int   g_srow[S_MAX];       // slot -> dst node
__device__ float g_sinv[S_MAX];       // slot -> 1/cnt
__device__ int   g_soff[S_MAX + 1];   // slot -> edge offset
__device__ int   g_scursor[S_MAX];
__device__ int   g_esrc[EE];          // edges sorted by slot: src node
__device__ int   g_dcnt[NN];
__device__ int   g_doff[NN + 1];
__device__ int   g_dcur[NN];
__device__ int   g_dslot[S_MAX];      // slots sorted by dst
__device__ unsigned long long g_bsum[NBLK];
__device__ unsigned long long g_bpre[NBLK];
__device__ int   g_roff[RR + 1];
__device__ int   g_S;
__device__ int   g_ntiles;
__device__ int   g_tile_w[MAX_RTILES];
__device__ int   g_tile_m0[MAX_RTILES];
__device__ int   g_tile_rows[MAX_RTILES];
__device__ float g_agg[(long long)S_MAX * DD];   // per-slot means (rna, k pair-permuted)
__device__ float g_msg[(long long)S_MAX * DD];
__device__ float g_h[NN * DD];                   // raw layer-1 hidden
__device__ float g_xr[NN * DD];                  // rna, pair-permuted copy of current X
__device__ unsigned int g_Wt[17 * NP * KK];      // tf32 W^T, k pair-permuted

// ---------------- helpers ----------------
__device__ __forceinline__ uint32_t s2u(const void* p) {
    uint32_t a;
    asm("{ .reg .u64 t; cvta.to.shared.u64 t, %1; cvt.u32.u64 %0, t; }" : "=r"(a) : "l"(p));
    return a;
}
__device__ __forceinline__ void cpa16(uint32_t dst, const void* src) {
    asm volatile("cp.async.cg.shared.global [%0], [%1], 16;" :: "r"(dst), "l"(src));
}
__device__ __forceinline__ void mma8(float& c0, float& c1, float& c2, float& c3,
                                     uint32_t a0, uint32_t a1, uint32_t a2, uint32_t a3,
                                     uint32_t b0, uint32_t b1) {
    asm volatile(
        "mma.sync.aligned.m16n8k8.row.col.f32.tf32.tf32.f32 "
        "{%0,%1,%2,%3},{%4,%5,%6,%7},{%8,%9},{%0,%1,%2,%3};"
        : "+f"(c0), "+f"(c1), "+f"(c2), "+f"(c3)
        : "r"(a0), "r"(a1), "r"(a2), "r"(a3), "r"(b0), "r"(b1));
}
__device__ __forceinline__ uint32_t rna(uint32_t x) {
    uint32_t t;
    asm("cvt.rna.tf32.f32 %0, %1;" : "=r"(t) : "r"(x));
    return t;
}
__device__ __forceinline__ float rnaf(float x) {
    return __uint_as_float(rna(__float_as_uint(x)));
}
// ks 8g..8g+3 in a, 8g+4..8g+7 in b -> interleaved pair layout {k0,k4,k1,k5},{k2,k6,k3,k7}
__device__ __forceinline__ void perm_store(float* base, float4 a, float4 b) {
    float4 w0 = make_float4(rnaf(a.x), rnaf(b.x), rnaf(a.y), rnaf(b.y));
    float4 w1 = make_float4(rnaf(a.z), rnaf(b.z), rnaf(a.w), rnaf(b.w));
    *(float4*)(base)     = w0;
    *(float4*)(base + 4) = w1;
}

// ---------------- preprocessing ----------------
__global__ void k_zero() {
    int i = blockIdx.x * blockDim.x + threadIdx.x;
    if (i < NB) g_cnt[i] = 0;
    if (i < S_MAX) g_scursor[i] = 0;
    if (i < NN) { g_dcnt[i] = 0; g_dcur[i] = 0; }
}
// g_xr = rna, pair-permuted copy of X (for root tiles)
__global__ void k_xr(const float* __restrict__ X) {
    int idx = blockIdx.x * blockDim.x + threadIdx.x;
    if (idx >= NN * 25) return;
    int n = idx / 25, g = idx % 25;
    const float4* x4 = (const float4*)X;
    float4 a = x4[n * 50 + 2 * g];
    float4 b = x4[n * 50 + 2 * g + 1];
    perm_store(g_xr + (long long)n * DD + 8 * g, a, b);
}
// g_Wt[w][n][kperm] = tf32_rna(W[w][k][n]); coalesced transpose
__global__ void k_wt(const float* __restrict__ W, const float* __restrict__ root) {
    __shared__ float st[32][33];
    int w  = blockIdx.z;
    int kt = blockIdx.y;
    int nt = blockIdx.x;
    int tx = threadIdx.x;
    #pragma unroll
    for (int q = 0; q < 4; q++) {
        int ky = threadIdx.y + 8 * q;
        int k = kt * 32 + ky;
        int n = nt * 32 + tx;
        float v = 0.0f;
        if (k < 200 && n < 200)
            v = (w < 16) ? W[w * 40000 + k * 200 + n] : root[k * 200 + n];
        st[ky][tx] = v;
    }
    __syncthreads();
    #pragma unroll
    for (int q = 0; q < 4; q++) {
        int ny = threadIdx.y + 8 * q;
        int n = nt * 32 + ny;
        int k = kt * 32 + tx;
        if (n < NP && k < 200) {
            int g = k >> 3, t = k & 7;
            int kp = (g << 3) + ((t & 3) << 1) + (t >> 2);
            g_Wt[w * (NP * KK) + n * KK + kp] = rna(__float_as_uint(st[tx][ny]));
        }
    }
}
__global__ void k_hist(const int* __restrict__ etype, const int* __restrict__ dst) {
    int i = blockIdx.x * blockDim.x + threadIdx.x;
    if (i < EE) atomicAdd(&g_cnt[etype[i] * NN + dst[i]], 1);
}
__global__ void k_scan1() {
    __shared__ unsigned long long wsum[8];
    int b = blockIdx.x, tid = threadIdx.x;
    int i0 = b * 2048 + tid * 8;
    unsigned long long t = 0;
    #pragma unroll
    for (int j = 0; j < 8; j++) {
        int i = i0 + j;
        if (i < NB) {
            int c = g_cnt[i];
            t += (((unsigned long long)c) << 32) | (unsigned)(c > 0);
        }
    }
    int lane = tid & 31, w = tid >> 5;
    #pragma unroll
    for (int o = 16; o > 0; o >>= 1) t += __shfl_down_sync(0xffffffffu, t, o);
    if (lane == 0) wsum[w] = t;
    __syncthreads();
    if (tid == 0) {
        unsigned long long s = 0;
        #pragma unroll
        for (int q = 0; q < 8; q++) s += wsum[q];
        g_bsum[b] = s;
    }
}
__global__ void k_scan2() {
    __shared__ unsigned long long sh[512];
    int tid = threadIdx.x;
    unsigned long long v = (tid < NBLK) ? g_bsum[tid] : 0ull;
    sh[tid] = v;
    __syncthreads();
    for (int off = 1; off < 512; off <<= 1) {
        unsigned long long u = (tid >= off) ? sh[tid - off] : 0ull;
        __syncthreads();
        sh[tid] += u;
        __syncthreads();
    }
    if (tid < NBLK) g_bpre[tid] = sh[tid] - v;
    if (tid == 511) {
        int S = (int)(sh[511] & 0xffffffffull);
        g_S = S;
        g_roff[RR] = S;
    }
}
__global__ void k_scan3() {
    __shared__ unsigned long long wsum[8];
    int b = blockIdx.x, tid = threadIdx.x;
    int i0 = b * 2048 + tid * 8;
    int cj[8];
    unsigned long long loc[8];
    unsigned long long t = 0;
    #pragma unroll
    for (int j = 0; j < 8; j++) {
        int i = i0 + j;
        int c = (i < NB) ? g_cnt[i] : 0;
        cj[j] = c;
        t += (((unsigned long long)c) << 32) | (unsigned)(c > 0);
        loc[j] = t;
    }
    int lane = tid & 31, w = tid >> 5;
    unsigned long long v = t;
    #pragma unroll
    for (int o = 1; o < 32; o <<= 1) {
        unsigned long long u = __shfl_up_sync(0xffffffffu, v, o);
        if (lane >= o) v += u;
    }
    unsigned long long texcl = v - t;
    if (lane == 31) wsum[w] = v;
    __syncthreads();
    if (tid == 0) {
        unsigned long long s = 0;
        #pragma unroll
        for (int q = 0; q < 8; q++) { unsigned long long x = wsum[q]; wsum[q] = s; s += x; }
    }
    __syncthreads();
    unsigned long long base = g_bpre[b] + wsum[w] + texcl;
    #pragma unroll
    for (int j = 0; j < 8; j++) {
        int i = i0 + j;
        if (i < NB) {
            unsigned long long elem = (((unsigned long long)cj[j]) << 32) | (unsigned)(cj[j] > 0);
            unsigned long long pre = base + loc[j] - elem;
            int run = (int)(pre & 0xffffffffull);
            if (i % NN == 0) g_roff[i / NN] = run;
            if (cj[j] > 0) {
                g_slotid[i] = run;
                g_srow[run] = i % NN;
                g_sinv[run] = 1.0f / (float)cj[j];
                g_soff[run] = (int)(pre >> 32);
            }
        }
    }
}
__global__ void k_tiles() {
    __shared__ int tb[RR + 1];
    int tid = threadIdx.x;
    if (tid == 0) {
        int t = 0;
        for (int r = 0; r < RR; r++) {
            tb[r] = t;
            int m = g_roff[r + 1] - g_roff[r];
            t += (m + TM - 1) / TM;
        }
        tb[RR] = t;
        g_ntiles = t;
        g_soff[g_S] = EE;
    }
    __syncthreads();
    int nt = tb[RR];
    for (int i = tid; i < nt; i += blockDim.x) {
        int r = 0;
        while (i >= tb[r + 1]) r++;
        int s0 = g_roff[r] + (i - tb[r]) * TM;
        g_tile_w[i] = r;
        g_tile_m0[i] = s0;
        g_tile_rows[i] = min(TM, g_roff[r + 1] - s0);
    }
}
__global__ void k_sortslot(const int* __restrict__ etype, const int* __restrict__ dst,
                           const int* __restrict__ src) {
    int i = blockIdx.x * blockDim.x + threadIdx.x;
    if (i >= EE) return;
    int slot = g_slotid[etype[i] * NN + dst[i]];
    int pos = g_soff[slot] + atomicAdd(&g_scursor[slot], 1);
    g_esrc[pos] = src[i];
}
__global__ void k_dcnt() {
    int i = blockIdx.x * blockDim.x + threadIdx.x;
    if (i < g_S) atomicAdd(&g_dcnt[g_srow[i]], 1);
}
__global__ void k_dscan() {
    __shared__ int wsum[32];
    int tid = threadIdx.x;
    int base = tid * 49;
    int s = 0;
    for (int j = 0; j < 49; j++) {
        int i = base + j;
        if (i < NN) s += g_dcnt[i];
    }
    int lane = tid & 31, w = tid >> 5;
    int v = s;
    #pragma unroll
    for (int o = 1; o < 32; o <<= 1) {
        int u = __shfl_up_sync(0xffffffffu, v, o);
        if (lane >= o) v += u;
    }
    if (lane == 31) wsum[w] = v;
    __syncthreads();
    if (w == 0) {
        int x = wsum[lane];
        int y = x;
        #pragma unroll
        for (int o = 1; o < 32; o <<= 1) {
            int u = __shfl_up_sync(0xffffffffu, y, o);
            if (lane >= o) y += u;
        }
        wsum[lane] = y - x;
    }
    __syncthreads();
    int run = wsum[w] + (v - s);
    for (int j = 0; j < 49; j++) {
        int i = base + j;
        if (i < NN) { g_doff[i] = run; run += g_dcnt[i]; }
    }
    if (tid == 1023) g_doff[NN] = run;
}
__global__ void k_sortdst() {
    int i = blockIdx.x * blockDim.x + threadIdx.x;
    if (i >= g_S) return;
    int d = g_srow[i];
    int pos = g_doff[d] + atomicAdd(&g_dcur[d], 1);
    g_dslot[pos] = i;
}

// segmented MEAN, rna + pair-permuted: g_agg[slot] = perm(rna((1/cnt) * sum x[src]))
__global__ void k_aggseg(const float* __restrict__ x) {
    int idx = blockIdx.x * blockDim.x + threadIdx.x;
    if (idx >= g_S * 25) return;
    int slot = idx / 25, g = idx % 25;
    int e0 = g_soff[slot], e1 = g_soff[slot + 1];
    float inv = g_sinv[slot];
    float4 a = make_float4(0.f, 0.f, 0.f, 0.f);
    float4 b = make_float4(0.f, 0.f, 0.f, 0.f);
    const float4* x4 = (const float4*)x;
    for (int j = e0; j < e1; j++) {
        int s = g_esrc[j];
        float4 ua = x4[s * 50 + 2 * g];
        float4 ub = x4[s * 50 + 2 * g + 1];
        a.x += ua.x; a.y += ua.y; a.z += ua.z; a.w += ua.w;
        b.x += ub.x; b.y += ub.y; b.z += ub.z; b.w += ub.w;
    }
    a.x *= inv; a.y *= inv; a.z *= inv; a.w *= inv;
    b.x *= inv; b.y *= inv; b.z *= inv; b.w *= inv;
    perm_store(g_agg + (long long)slot * DD + 8 * g, a, b);
}

// out[n] += sum over n's slots of g_msg[slot]; optional relu; optional g_xr update
__global__ void k_gather(float* __restrict__ out, int do_relu, int wr_xr) {
    int idx = blockIdx.x * blockDim.x + threadIdx.x;
    if (idx >= NN * 25) return;
    int n = idx / 25, g = idx % 25;
    float4* o4 = (float4*)out;
    float4 a = o4[n * 50 + 2 * g];
    float4 b = o4[n * 50 + 2 * g + 1];
    int j0 = g_doff[n], j1 = g_doff[n + 1];
    const float4* m4 = (const float4*)g_msg;
    for (int j = j0; j < j1; j++) {
        long long sl = g_dslot[j];
        float4 ua = m4[sl * 50 + 2 * g];
        float4 ub = m4[sl * 50 + 2 * g + 1];
        a.x += ua.x; a.y += ua.y; a.z += ua.z; a.w += ua.w;
        b.x += ub.x; b.y += ub.y; b.z += ub.z; b.w += ub.w;
    }
    if (do_relu) {
        a.x = fmaxf(a.x, 0.f); a.y = fmaxf(a.y, 0.f);
        a.z = fmaxf(a.z, 0.f); a.w = fmaxf(a.w, 0.f);
        b.x = fmaxf(b.x, 0.f); b.y = fmaxf(b.y, 0.f);
        b.z = fmaxf(b.z, 0.f); b.w = fmaxf(b.w, 0.f);
    }
    o4[n * 50 + 2 * g]     = a;
    o4[n * 50 + 2 * g + 1] = b;
    if (wr_xr) perm_store(g_xr + (long long)n * DD + 8 * g, a, b);
}

// ---------------- tf32 mma.sync GEMM ----------------
// mode 0: grid=ROOT_TILES; out[m0+row] = g_xr[m0+row]@Wt[16] + bias
// mode 1: grid=MAX_RTILES; g_msg[slot] = g_agg[slot] @ Wt[r]
// 12 warps; warp grid 4(M) x 3(N); warp tile 32 x 72; A/B pair-permuted LDS.64.
__global__ __launch_bounds__(NTHREADS, 1)
void k_mma(float* __restrict__ out, const float* __restrict__ bias, int mode) {
    extern __shared__ __align__(16) char smem_raw[];
    int t = blockIdx.x;
    int wsel, m0, rows;
    if (mode == 0) {
        wsel = 16; m0 = t * TM; rows = min(TM, NN - m0);
    } else {
        if (t >= g_ntiles) return;
        wsel = g_tile_w[t]; m0 = g_tile_m0[t]; rows = g_tile_rows[t];
    }

    uint32_t sb = s2u(smem_raw);
    const float* As = (const float*)smem_raw;
    int tid = threadIdx.x;
    int wid = tid >> 5, lane = tid & 31;
    int wm = wid & 3, wn = wid >> 2;
    int r4 = lane >> 2, c4 = lane & 3;

    const unsigned int* Wt = g_Wt + wsel * (NP * KK);
    const float* Ab = (mode == 0) ? g_xr : (const float*)g_agg;

    // stage A (group 0)
    for (int q = tid; q < TM * 50; q += NTHREADS) {
        int row = q / 50, s = q % 50;
        int gr = m0 + min(row, rows - 1);
        cpa16(sb + SM_A + q * 16 - (q - row * 50) * 0, Ab + (long long)gr * DD + s * 4);
    }
    asm volatile("cp.async.commit_group;" ::: "memory");
    // stage B chunks 0,1 (groups 1,2)
    #pragma unroll
    for (int pc = 0; pc < 2; pc++) {
        uint32_t bo = sb + (pc ? SM_B1 : SM_B0);
        for (int q = tid; q < NP * 10; q += NTHREADS) {
            int n = q / 10, h = q % 10;
            cpa16(bo + n * (BSTRIDE * 4) + h * 16, Wt + n * KK + pc * 40 + h * 4);
        }
        asm volatile("cp.async.commit_group;" ::: "memory");
    }

    float creg[2][9][4];
    #pragma unroll
    for (int mi = 0; mi < 2; mi++)
        #pragma unroll
        for (int ni = 0; ni < 9; ni++)
            #pragma unroll
            for (int q = 0; q < 4; q++) creg[mi][ni][q] = 0.0f;

    int arow0 = wm * 32 + r4;
    int bn0 = wn * 72 + r4;

    for (int cch = 0; cch < 5; cch++) {
        if (cch < 4) asm volatile("cp.async.wait_group 1;" ::: "memory");
        else         asm volatile("cp.async.wait_group 0;" ::: "memory");
        __syncthreads();

        const uint32_t* Bs = (const uint32_t*)(smem_raw + ((cch & 1) ? SM_B1 : SM_B0));
        #pragma unroll
        for (int kk = 0; kk < 5; kk++) {
            uint2 a01[2], a23[2];
            #pragma unroll
            for (int mi = 0; mi < 2; mi++) {
                const float* ap = As + (arow0 + mi * 16) * ASTRIDE + cch * 40 + kk * 8 + 2 * c4;
                a01[mi] = *(const uint2*)ap;                 // a0, a2
                a23[mi] = *(const uint2*)(ap + 8 * ASTRIDE); // a1, a3
            }
            #pragma unroll
            for (int ni = 0; ni < 9; ni++) {
                uint2 b = *(const uint2*)(Bs + (bn0 + ni * 8) * BSTRIDE + kk * 8 + 2 * c4);
                #pragma unroll
                for (int mi = 0; mi < 2; mi++)
                    mma8(creg[mi][ni][0], creg[mi][ni][1], creg[mi][ni][2], creg[mi][ni][3],
                         a01[mi].x, a23[mi].x, a01[mi].y, a23[mi].y, b.x, b.y);
            }
        }
        __syncthreads();
        if (cch + 2 < 5) {
            uint32_t bo = sb + ((cch & 1) ? SM_B1 : SM_B0);
            int kc = (cch + 2) * 40;
            for (int q = tid; q < NP * 10; q += NTHREADS) {
                int n = q / 10, h = q % 10;
                cpa16(bo + n * (BSTRIDE * 4) + h * 16, Wt + n * KK + kc + h * 4);
            }
            asm volatile("cp.async.commit_group;" ::: "memory");
        }
    }

    // epilogue: plain stores only
    #pragma unroll
    for (int mi = 0; mi < 2; mi++) {
        #pragma unroll
        for (int rr = 0; rr < 2; rr++) {
            int row = wm * 32 + mi * 16 + rr * 8 + r4;
            if (row < rows) {
                float* ob = (mode == 0) ? (out + (long long)(m0 + row) * DD)
                                        : (g_msg + (long long)(m0 + row) * DD);
                #pragma unroll
                for (int ni = 0; ni < 9; ni++) {
                    int col = wn * 72 + ni * 8 + 2 * c4;
                    if (col < 200) {
                        float2 o;
                        o.x = creg[mi][ni][2 * rr];
                        o.y = creg[mi][ni][2 * rr + 1];
                        if (mode == 0) { o.x += bias[col]; o.y += bias[col + 1]; }
                        *(float2*)(ob + col) = o;
                    }
                }
            }
        }
    }
}

// ---------------- launch ----------------
extern "C" void kernel_launch(void* const* d_in, const int* in_sizes, int n_in,
                              void* d_out, int out_size) {
    const int*   edge_index = (const int*)d_in[0];
    const int*   etype      = (const int*)d_in[1];
    const float* emb        = (const float*)d_in[2];
    const float* W1         = (const float*)d_in[3];
    const float* root1      = (const float*)d_in[4];
    const float* b1         = (const float*)d_in[5];
    const float* W2         = (const float*)d_in[6];
    const float* root2      = (const float*)d_in[7];
    const float* b2         = (const float*)d_in[8];
    float* out = (float*)d_out;

    const int* src = edge_index;
    const int* dst = edge_index + EE;

    cudaFuncSetAttribute(k_mma, cudaFuncAttributeMaxDynamicSharedMemorySize, SM_TOTAL);

    int gridNB = (NB + 255) / 256;
    int gridE  = (EE + 255) / 256;
    int gridS  = (S_MAX + 255) / 256;
    int gridSeg = (S_MAX * 25 + 255) / 256;
    int gridG  = (NN * 25 + 255) / 256;
    dim3 gridWt(7, 7, 17), blkWt(32, 8);

    // launch idx 3 = k_mma(root) -> this is the launch ncu profiles
    k_zero<<<gridNB, 256>>>();                                   // 0
    k_xr<<<gridG, 256>>>(emb);                                   // 1
    k_wt<<<gridWt, blkWt>>>(W1, root1);                          // 2
    k_mma<<<ROOT_TILES, NTHREADS, SM_TOTAL>>>(g_h, b1, 0);       // 3  <-- PROFILED

    // edge preprocessing
    k_hist<<<gridE, 256>>>(etype, dst);
    k_scan1<<<NBLK, 256>>>();
    k_scan2<<<1, 512>>>();
    k_scan3<<<NBLK, 256>>>();
    k_tiles<<<1, 256>>>();
    k_sortslot<<<gridE, 256>>>(etype, dst, src);
    k_dcnt<<<gridS, 256>>>();
    k_dscan<<<1, 1024>>>();
    k_sortdst<<<gridS, 256>>>();

    // layer 1 (root part already in g_h)
    k_aggseg<<<gridSeg, 256>>>(emb);
    k_mma<<<MAX_RTILES, NTHREADS, SM_TOTAL>>>(g_h, b1, 1);
    k_gather<<<gridG, 256>>>(g_h, 1, 1);    // h complete + relu; writes g_xr

    // layer 2
    k_wt<<<gridWt, blkWt>>>(W2, root2);
    k_aggseg<<<gridSeg, 256>>>(g_h);
    k_mma<<<ROOT_TILES, NTHREADS, SM_TOTAL>>>(out, b2, 0);
    k_mma<<<MAX_RTILES, NTHREADS, SM_TOTAL>>>(out, b2, 1);
    k_gather<<<gridG, 256>>>(out, 0, 0);
}

// round 14
// speedup vs baseline: 1.0557x; 1.0557x over previous
#include <cuda_runtime.h>
#include <cstdint>

// Problem constants
#define NN 50000
#define RR 16
#define DD 200
#define EE 400000
#define NB (RR * NN)
#define S_MAX (EE + 256)
#define NBLK ((NB + 2047) / 2048)

#define TM 64
#define ROOT_TILES ((NN + TM - 1) / TM)    // 782
#define MAX_RTILES 6600

#define NP 224                  // padded N (4 warps x 56)
#define KK 200                  // K (g_Wt row length)
#define KCH 40                  // K chunk (words)

#define NTHREADS 256            // 8 warps: 2(M) x 4(N)

// smem: double-buffered A chunk + B chunk
#define ABUF (TM * KCH * 4)                  // 10240
#define BBUF (NP * KCH * 4)                  // 35840
#define SM_TOTAL (2 * ABUF + 2 * BBUF + 64)  // 92224 -> 2 CTAs/SM

// ---------------- device scratch ----------------
__device__ int   g_cnt[NB];
__device__ int   g_slotid[NB];
__device__ int   g_srow[S_MAX];       // slot -> dst node
__device__ float g_sinv[S_MAX];       // slot -> 1/cnt
__device__ int   g_soff[S_MAX + 1];   // slot -> edge offset
__device__ int   g_scursor[S_MAX];
__device__ int   g_esrc[EE];          // edges sorted by slot: src node
__device__ int   g_dcnt[NN];
__device__ int   g_doff[NN + 1];
__device__ int   g_dcur[NN];
__device__ int   g_dslot[S_MAX];      // slots sorted by dst
__device__ unsigned long long g_bsum[NBLK];
__device__ unsigned long long g_bpre[NBLK];
__device__ int   g_roff[RR + 1];
__device__ int   g_S;
__device__ int   g_ntiles;
__device__ int   g_tile_w[MAX_RTILES];
__device__ int   g_tile_m0[MAX_RTILES];
__device__ int   g_tile_rows[MAX_RTILES];
__device__ float g_agg[(long long)S_MAX * DD];   // per-slot means (rna, pair-permuted)
__device__ float g_msg[(long long)S_MAX * DD];
__device__ float g_h[NN * DD];                   // raw layer-1 hidden
__device__ float g_xr[NN * DD];                  // rna, pair-permuted copy of current X
__device__ unsigned int g_Wt[17 * NP * KK];      // tf32 W^T, k pair-permuted

// ---------------- helpers ----------------
__device__ __forceinline__ uint32_t s2u(const void* p) {
    uint32_t a;
    asm("{ .reg .u64 t; cvta.to.shared.u64 t, %1; cvt.u32.u64 %0, t; }" : "=r"(a) : "l"(p));
    return a;
}
__device__ __forceinline__ void cpa16(uint32_t dst, const void* src) {
    asm volatile("cp.async.cg.shared.global [%0], [%1], 16;" :: "r"(dst), "l"(src));
}
__device__ __forceinline__ void mma8(float& c0, float& c1, float& c2, float& c3,
                                     uint32_t a0, uint32_t a1, uint32_t a2, uint32_t a3,
                                     uint32_t b0, uint32_t b1) {
    asm volatile(
        "mma.sync.aligned.m16n8k8.row.col.f32.tf32.tf32.f32 "
        "{%0,%1,%2,%3},{%4,%5,%6,%7},{%8,%9},{%0,%1,%2,%3};"
        : "+f"(c0), "+f"(c1), "+f"(c2), "+f"(c3)
        : "r"(a0), "r"(a1), "r"(a2), "r"(a3), "r"(b0), "r"(b1));
}
__device__ __forceinline__ uint32_t rna(uint32_t x) {
    uint32_t t;
    asm("cvt.rna.tf32.f32 %0, %1;" : "=r"(t) : "r"(x));
    return t;
}
__device__ __forceinline__ float rnaf(float x) {
    return __uint_as_float(rna(__float_as_uint(x)));
}
// ks 8g..8g+3 in a, 8g+4..8g+7 in b -> interleaved pair layout {k0,k4,k1,k5},{k2,k6,k3,k7}
__device__ __forceinline__ void perm_store(float* base, float4 a, float4 b) {
    float4 w0 = make_float4(rnaf(a.x), rnaf(b.x), rnaf(a.y), rnaf(b.y));
    float4 w1 = make_float4(rnaf(a.z), rnaf(b.z), rnaf(a.w), rnaf(b.w));
    *(float4*)(base)     = w0;
    *(float4*)(base + 4) = w1;
}

// ---------------- preprocessing ----------------
__global__ void k_zero() {
    int i = blockIdx.x * blockDim.x + threadIdx.x;
    if (i < NB) g_cnt[i] = 0;
    if (i < S_MAX) g_scursor[i] = 0;
    if (i < NN) { g_dcnt[i] = 0; g_dcur[i] = 0; }
}
// g_xr = rna, pair-permuted copy of X (for root tiles)
__global__ void k_xr(const float* __restrict__ X) {
    int idx = blockIdx.x * blockDim.x + threadIdx.x;
    if (idx >= NN * 25) return;
    int n = idx / 25, g = idx % 25;
    const float4* x4 = (const float4*)X;
    float4 a = x4[n * 50 + 2 * g];
    float4 b = x4[n * 50 + 2 * g + 1];
    perm_store(g_xr + (long long)n * DD + 8 * g, a, b);
}
// g_Wt[w][n][kperm] = tf32_rna(W[w][k][n]); coalesced transpose
__global__ void k_wt(const float* __restrict__ W, const float* __restrict__ root) {
    __shared__ float st[32][33];
    int w  = blockIdx.z;
    int kt = blockIdx.y;
    int nt = blockIdx.x;
    int tx = threadIdx.x;
    #pragma unroll
    for (int q = 0; q < 4; q++) {
        int ky = threadIdx.y + 8 * q;
        int k = kt * 32 + ky;
        int n = nt * 32 + tx;
        float v = 0.0f;
        if (k < 200 && n < 200)
            v = (w < 16) ? W[w * 40000 + k * 200 + n] : root[k * 200 + n];
        st[ky][tx] = v;
    }
    __syncthreads();
    #pragma unroll
    for (int q = 0; q < 4; q++) {
        int ny = threadIdx.y + 8 * q;
        int n = nt * 32 + ny;
        int k = kt * 32 + tx;
        if (n < NP && k < 200) {
            int g = k >> 3, t = k & 7;
            int kp = (g << 3) + ((t & 3) << 1) + (t >> 2);
            g_Wt[w * (NP * KK) + n * KK + kp] = rna(__float_as_uint(st[tx][ny]));
        }
    }
}
__global__ void k_hist(const int* __restrict__ etype, const int* __restrict__ dst) {
    int i = blockIdx.x * blockDim.x + threadIdx.x;
    if (i < EE) atomicAdd(&g_cnt[etype[i] * NN + dst[i]], 1);
}
__global__ void k_scan1() {
    __shared__ unsigned long long wsum[8];
    int b = blockIdx.x, tid = threadIdx.x;
    int i0 = b * 2048 + tid * 8;
    unsigned long long t = 0;
    #pragma unroll
    for (int j = 0; j < 8; j++) {
        int i = i0 + j;
        if (i < NB) {
            int c = g_cnt[i];
            t += (((unsigned long long)c) << 32) | (unsigned)(c > 0);
        }
    }
    int lane = tid & 31, w = tid >> 5;
    #pragma unroll
    for (int o = 16; o > 0; o >>= 1) t += __shfl_down_sync(0xffffffffu, t, o);
    if (lane == 0) wsum[w] = t;
    __syncthreads();
    if (tid == 0) {
        unsigned long long s = 0;
        #pragma unroll
        for (int q = 0; q < 8; q++) s += wsum[q];
        g_bsum[b] = s;
    }
}
__global__ void k_scan2() {
    __shared__ unsigned long long sh[512];
    int tid = threadIdx.x;
    unsigned long long v = (tid < NBLK) ? g_bsum[tid] : 0ull;
    sh[tid] = v;
    __syncthreads();
    for (int off = 1; off < 512; off <<= 1) {
        unsigned long long u = (tid >= off) ? sh[tid - off] : 0ull;
        __syncthreads();
        sh[tid] += u;
        __syncthreads();
    }
    if (tid < NBLK) g_bpre[tid] = sh[tid] - v;
    if (tid == 511) {
        int S = (int)(sh[511] & 0xffffffffull);
        g_S = S;
        g_roff[RR] = S;
    }
}
__global__ void k_scan3() {
    __shared__ unsigned long long wsum[8];
    int b = blockIdx.x, tid = threadIdx.x;
    int i0 = b * 2048 + tid * 8;
    int cj[8];
    unsigned long long loc[8];
    unsigned long long t = 0;
    #pragma unroll
    for (int j = 0; j < 8; j++) {
        int i = i0 + j;
        int c = (i < NB) ? g_cnt[i] : 0;
        cj[j] = c;
        t += (((unsigned long long)c) << 32) | (unsigned)(c > 0);
        loc[j] = t;
    }
    int lane = tid & 31, w = tid >> 5;
    unsigned long long v = t;
    #pragma unroll
    for (int o = 1; o < 32; o <<= 1) {
        unsigned long long u = __shfl_up_sync(0xffffffffu, v, o);
        if (lane >= o) v += u;
    }
    unsigned long long texcl = v - t;
    if (lane == 31) wsum[w] = v;
    __syncthreads();
    if (tid == 0) {
        unsigned long long s = 0;
        #pragma unroll
        for (int q = 0; q < 8; q++) { unsigned long long x = wsum[q]; wsum[q] = s; s += x; }
    }
    __syncthreads();
    unsigned long long base = g_bpre[b] + wsum[w] + texcl;
    #pragma unroll
    for (int j = 0; j < 8; j++) {
        int i = i0 + j;
        if (i < NB) {
            unsigned long long elem = (((unsigned long long)cj[j]) << 32) | (unsigned)(cj[j] > 0);
            unsigned long long pre = base + loc[j] - elem;
            int run = (int)(pre & 0xffffffffull);
            if (i % NN == 0) g_roff[i / NN] = run;
            if (cj[j] > 0) {
                g_slotid[i] = run;
                g_srow[run] = i % NN;
                g_sinv[run] = 1.0f / (float)cj[j];
                g_soff[run] = (int)(pre >> 32);
            }
        }
    }
}
__global__ void k_tiles() {
    __shared__ int tb[RR + 1];
    int tid = threadIdx.x;
    if (tid == 0) {
        int t = 0;
        for (int r = 0; r < RR; r++) {
            tb[r] = t;
            int m = g_roff[r + 1] - g_roff[r];
            t += (m + TM - 1) / TM;
        }
        tb[RR] = t;
        g_ntiles = t;
        g_soff[g_S] = EE;
    }
    __syncthreads();
    int nt = tb[RR];
    for (int i = tid; i < nt; i += blockDim.x) {
        int r = 0;
        while (i >= tb[r + 1]) r++;
        int s0 = g_roff[r] + (i - tb[r]) * TM;
        g_tile_w[i] = r;
        g_tile_m0[i] = s0;
        g_tile_rows[i] = min(TM, g_roff[r + 1] - s0);
    }
}
__global__ void k_sortslot(const int* __restrict__ etype, const int* __restrict__ dst,
                           const int* __restrict__ src) {
    int i = blockIdx.x * blockDim.x + threadIdx.x;
    if (i >= EE) return;
    int slot = g_slotid[etype[i] * NN + dst[i]];
    int pos = g_soff[slot] + atomicAdd(&g_scursor[slot], 1);
    g_esrc[pos] = src[i];
}
__global__ void k_dcnt() {
    int i = blockIdx.x * blockDim.x + threadIdx.x;
    if (i < g_S) atomicAdd(&g_dcnt[g_srow[i]], 1);
}
__global__ void k_dscan() {
    __shared__ int wsum[32];
    int tid = threadIdx.x;
    int base = tid * 49;
    int s = 0;
    for (int j = 0; j < 49; j++) {
        int i = base + j;
        if (i < NN) s += g_dcnt[i];
    }
    int lane = tid & 31, w = tid >> 5;
    int v = s;
    #pragma unroll
    for (int o = 1; o < 32; o <<= 1) {
        int u = __shfl_up_sync(0xffffffffu, v, o);
        if (lane >= o) v += u;
    }
    if (lane == 31) wsum[w] = v;
    __syncthreads();
    if (w == 0) {
        int x = wsum[lane];
        int y = x;
        #pragma unroll
        for (int o = 1; o < 32; o <<= 1) {
            int u = __shfl_up_sync(0xffffffffu, y, o);
            if (lane >= o) y += u;
        }
        wsum[lane] = y - x;
    }
    __syncthreads();
    int run = wsum[w] + (v - s);
    for (int j = 0; j < 49; j++) {
        int i = base + j;
        if (i < NN) { g_doff[i] = run; run += g_dcnt[i]; }
    }
    if (tid == 1023) g_doff[NN] = run;
}
__global__ void k_sortdst() {
    int i = blockIdx.x * blockDim.x + threadIdx.x;
    if (i >= g_S) return;
    int d = g_srow[i];
    int pos = g_doff[d] + atomicAdd(&g_dcur[d], 1);
    g_dslot[pos] = i;
}

// segmented MEAN, rna + pair-permuted
__global__ void k_aggseg(const float* __restrict__ x) {
    int idx = blockIdx.x * blockDim.x + threadIdx.x;
    if (idx >= g_S * 25) return;
    int slot = idx / 25, g = idx % 25;
    int e0 = g_soff[slot], e1 = g_soff[slot + 1];
    float inv = g_sinv[slot];
    float4 a = make_float4(0.f, 0.f, 0.f, 0.f);
    float4 b = make_float4(0.f, 0.f, 0.f, 0.f);
    const float4* x4 = (const float4*)x;
    for (int j = e0; j < e1; j++) {
        int s = g_esrc[j];
        float4 ua = x4[s * 50 + 2 * g];
        float4 ub = x4[s * 50 + 2 * g + 1];
        a.x += ua.x; a.y += ua.y; a.z += ua.z; a.w += ua.w;
        b.x += ub.x; b.y += ub.y; b.z += ub.z; b.w += ub.w;
    }
    a.x *= inv; a.y *= inv; a.z *= inv; a.w *= inv;
    b.x *= inv; b.y *= inv; b.z *= inv; b.w *= inv;
    perm_store(g_agg + (long long)slot * DD + 8 * g, a, b);
}

// out[n] += sum over n's slots of g_msg[slot]; optional relu; optional g_xr update
__global__ void k_gather(float* __restrict__ out, int do_relu, int wr_xr) {
    int idx = blockIdx.x * blockDim.x + threadIdx.x;
    if (idx >= NN * 25) return;
    int n = idx / 25, g = idx % 25;
    float4* o4 = (float4*)out;
    float4 a = o4[n * 50 + 2 * g];
    float4 b = o4[n * 50 + 2 * g + 1];
    int j0 = g_doff[n], j1 = g_doff[n + 1];
    const float4* m4 = (const float4*)g_msg;
    for (int j = j0; j < j1; j++) {
        long long sl = g_dslot[j];
        float4 ua = m4[sl * 50 + 2 * g];
        float4 ub = m4[sl * 50 + 2 * g + 1];
        a.x += ua.x; a.y += ua.y; a.z += ua.z; a.w += ua.w;
        b.x += ub.x; b.y += ub.y; b.z += ub.z; b.w += ub.w;
    }
    if (do_relu) {
        a.x = fmaxf(a.x, 0.f); a.y = fmaxf(a.y, 0.f);
        a.z = fmaxf(a.z, 0.f); a.w = fmaxf(a.w, 0.f);
        b.x = fmaxf(b.x, 0.f); b.y = fmaxf(b.y, 0.f);
        b.z = fmaxf(b.z, 0.f); b.w = fmaxf(b.w, 0.f);
    }
    o4[n * 50 + 2 * g]     = a;
    o4[n * 50 + 2 * g + 1] = b;
    if (wr_xr) perm_store(g_xr + (long long)n * DD + 8 * g, a, b);
}

// ---------------- tf32 mma.sync GEMM: fully pipelined A+B chunk streaming ----------------
// mode 0: grid=ROOT_TILES; out[m0+row] = g_xr[m0+row]@Wt[16] + bias
// mode 1: grid=MAX_RTILES; g_msg[slot] = g_agg[slot] @ Wt[r]
// 8 warps; warp grid 2(M) x 4(N); warp tile 32 x 56; 2 CTAs/SM.
__global__ __launch_bounds__(NTHREADS, 2)
void k_mma(float* __restrict__ out, const float* __restrict__ bias, int mode) {
    extern __shared__ __align__(16) char smem_raw[];
    int t = blockIdx.x;
    int wsel, m0, rows;
    if (mode == 0) {
        wsel = 16; m0 = t * TM; rows = min(TM, NN - m0);
    } else {
        if (t >= g_ntiles) return;
        wsel = g_tile_w[t]; m0 = g_tile_m0[t]; rows = g_tile_rows[t];
    }

    uint32_t sb = s2u(smem_raw);
    int tid = threadIdx.x;
    int wid = tid >> 5, lane = tid & 31;
    int wm = wid & 1, wn = wid >> 1;       // 2(M) x 4(N)
    int r4 = lane >> 2, c4 = lane & 3;

    const unsigned int* Wt = g_Wt + wsel * (NP * KK);
    const float* Ab = (mode == 0) ? g_xr : (const float*)g_agg;

    // stage chunks 0,1 (A + B together per group)
    #pragma unroll
    for (int pc = 0; pc < 2; pc++) {
        uint32_t abo = sb + pc * ABUF;
        for (int q = tid; q < TM * 10; q += NTHREADS) {
            int row = q / 10, h = q % 10;
            int gr = m0 + min(row, rows - 1);
            cpa16(abo + row * (KCH * 4) + h * 16, Ab + (long long)gr * DD + pc * KCH + h * 4);
        }
        uint32_t bbo = sb + 2 * ABUF + pc * BBUF;
        for (int q = tid; q < NP * 10; q += NTHREADS) {
            int n = q / 10, h = q % 10;
            cpa16(bbo + n * (KCH * 4) + h * 16, Wt + n * KK + pc * KCH + h * 4);
        }
        asm volatile("cp.async.commit_group;" ::: "memory");
    }

    float creg[2][7][4];
    #pragma unroll
    for (int mi = 0; mi < 2; mi++)
        #pragma unroll
        for (int ni = 0; ni < 7; ni++)
            #pragma unroll
            for (int q = 0; q < 4; q++) creg[mi][ni][q] = 0.0f;

    int arow0 = wm * 32 + r4;
    int bn0 = wn * 56 + r4;

    for (int cch = 0; cch < 5; cch++) {
        if (cch < 4) asm volatile("cp.async.wait_group 1;" ::: "memory");
        else         asm volatile("cp.async.wait_group 0;" ::: "memory");
        __syncthreads();

        const float* As = (const float*)(smem_raw + (cch & 1) * ABUF);
        const uint32_t* Bs = (const uint32_t*)(smem_raw + 2 * ABUF + (cch & 1) * BBUF);
        #pragma unroll
        for (int kk = 0; kk < 5; kk++) {
            uint2 a01[2], a23[2];
            #pragma unroll
            for (int mi = 0; mi < 2; mi++) {
                const float* ap = As + (arow0 + mi * 16) * KCH + kk * 8 + 2 * c4;
                a01[mi] = *(const uint2*)ap;               // a0, a2
                a23[mi] = *(const uint2*)(ap + 8 * KCH);   // a1, a3
            }
            #pragma unroll
            for (int ni = 0; ni < 7; ni++) {
                uint2 b = *(const uint2*)(Bs + (bn0 + ni * 8) * KCH + kk * 8 + 2 * c4);
                #pragma unroll
                for (int mi = 0; mi < 2; mi++)
                    mma8(creg[mi][ni][0], creg[mi][ni][1], creg[mi][ni][2], creg[mi][ni][3],
                         a01[mi].x, a23[mi].x, a01[mi].y, a23[mi].y, b.x, b.y);
            }
        }
        __syncthreads();
        if (cch + 2 < 5) {
            int pc = cch + 2;
            uint32_t abo = sb + (cch & 1) * ABUF;
            for (int q = tid; q < TM * 10; q += NTHREADS) {
                int row = q / 10, h = q % 10;
                int gr = m0 + min(row, rows - 1);
                cpa16(abo + row * (KCH * 4) + h * 16, Ab + (long long)gr * DD + pc * KCH + h * 4);
            }
            uint32_t bbo = sb + 2 * ABUF + (cch & 1) * BBUF;
            for (int q = tid; q < NP * 10; q += NTHREADS) {
                int n = q / 10, h = q % 10;
                cpa16(bbo + n * (KCH * 4) + h * 16, Wt + n * KK + pc * KCH + h * 4);
            }
            asm volatile("cp.async.commit_group;" ::: "memory");
        }
    }

    // epilogue: plain stores only
    #pragma unroll
    for (int mi = 0; mi < 2; mi++) {
        #pragma unroll
        for (int rr = 0; rr < 2; rr++) {
            int row = wm * 32 + mi * 16 + rr * 8 + r4;
            if (row < rows) {
                float* ob = (mode == 0) ? (out + (long long)(m0 + row) * DD)
                                        : (g_msg + (long long)(m0 + row) * DD);
                #pragma unroll
                for (int ni = 0; ni < 7; ni++) {
                    int col = wn * 56 + ni * 8 + 2 * c4;
                    if (col < 200) {
                        float2 o;
                        o.x = creg[mi][ni][2 * rr];
                        o.y = creg[mi][ni][2 * rr + 1];
                        if (mode == 0) { o.x += bias[col]; o.y += bias[col + 1]; }
                        *(float2*)(ob + col) = o;
                    }
                }
            }
        }
    }
}

// ---------------- launch ----------------
extern "C" void kernel_launch(void* const* d_in, const int* in_sizes, int n_in,
                              void* d_out, int out_size) {
    const int*   edge_index = (const int*)d_in[0];
    const int*   etype      = (const int*)d_in[1];
    const float* emb        = (const float*)d_in[2];
    const float* W1         = (const float*)d_in[3];
    const float* root1      = (const float*)d_in[4];
    const float* b1         = (const float*)d_in[5];
    const float* W2         = (const float*)d_in[6];
    const float* root2      = (const float*)d_in[7];
    const float* b2         = (const float*)d_in[8];
    float* out = (float*)d_out;

    const int* src = edge_index;
    const int* dst = edge_index + EE;

    cudaFuncSetAttribute(k_mma, cudaFuncAttributeMaxDynamicSharedMemorySize, SM_TOTAL);

    int gridNB = (NB + 255) / 256;
    int gridE  = (EE + 255) / 256;
    int gridS  = (S_MAX + 255) / 256;
    int gridSeg = (S_MAX * 25 + 255) / 256;
    int gridG  = (NN * 25 + 255) / 256;
    dim3 gridWt(7, 7, 17), blkWt(32, 8);

    // launch idx 3 = k_mma(root) -> this is the launch ncu profiles
    k_zero<<<gridNB, 256>>>();                                   // 0
    k_xr<<<gridG, 256>>>(emb);                                   // 1
    k_wt<<<gridWt, blkWt>>>(W1, root1);                          // 2
    k_mma<<<ROOT_TILES, NTHREADS, SM_TOTAL>>>(g_h, b1, 0);       // 3  <-- PROFILED

    // edge preprocessing
    k_hist<<<gridE, 256>>>(etype, dst);
    k_scan1<<<NBLK, 256>>>();
    k_scan2<<<1, 512>>>();
    k_scan3<<<NBLK, 256>>>();
    k_tiles<<<1, 256>>>();
    k_sortslot<<<gridE, 256>>>(etype, dst, src);
    k_dcnt<<<gridS, 256>>>();
    k_dscan<<<1, 1024>>>();
    k_sortdst<<<gridS, 256>>>();

    // layer 1 (root part already in g_h)
    k_aggseg<<<gridSeg, 256>>>(emb);
    k_mma<<<MAX_RTILES, NTHREADS, SM_TOTAL>>>(g_h, b1, 1);
    k_gather<<<gridG, 256>>>(g_h, 1, 1);    // h complete + relu; writes g_xr

    // layer 2
    k_wt<<<gridWt, blkWt>>>(W2, root2);
    k_aggseg<<<gridSeg, 256>>>(g_h);
    k_mma<<<ROOT_TILES, NTHREADS, SM_TOTAL>>>(out, b2, 0);
    k_mma<<<MAX_RTILES, NTHREADS, SM_TOTAL>>>(out, b2, 1);
    k_gather<<<gridG, 256>>>(out, 0, 0);
}